// round 2
// baseline (speedup 1.0000x reference)
#include <cuda_runtime.h>
#include <math.h>

// Problem constants
#define BB   16
#define HH   56
#define WW   56
#define CC   96
#define LL_  3136        // 56*56
#define NHD  3
#define WS_  7
#define TT   49          // tokens per window
#define HID_ 384
#define NCL_ 128
#define TWOH 768

// scratch (device globals — no allocation allowed)
__device__ float d_x1[BB * LL_ * CC];       // residual after attention
__device__ float d_maskT[TWOH * NCL_];      // binarized tm_inc, transposed [i][j]
__device__ float d_pinT[CC * HID_];         // pin_w transposed [c][h]
__device__ float d_qkvT[CC * 288];          // qkv_w transposed [c][o]
__device__ float d_projT[CC * CC];          // proj_w transposed [c][o]

// ---------------------------------------------------------------------------
// Prep: binarize mask (sigmoid(t)>0.5 <=> t>0) and transpose weights
// ---------------------------------------------------------------------------
__global__ void prep_kernel(const float* __restrict__ tm_inc,
                            const float* __restrict__ pin_w,
                            const float* __restrict__ qkv_w,
                            const float* __restrict__ proj_w) {
    int i = blockIdx.x * 256 + threadIdx.x;
    if (i < NCL_ * TWOH) {
        int j = i / TWOH, k = i - j * TWOH;
        d_maskT[k * NCL_ + j] = (tm_inc[i] > 0.0f) ? 1.0f : 0.0f;
        return;
    }
    i -= NCL_ * TWOH;
    if (i < HID_ * CC) {
        int h = i / CC, c = i - h * CC;
        d_pinT[c * HID_ + h] = pin_w[i];
        return;
    }
    i -= HID_ * CC;
    if (i < 288 * CC) {
        int o = i / CC, c = i - o * CC;
        d_qkvT[c * 288 + o] = qkv_w[i];
        return;
    }
    i -= 288 * CC;
    if (i < CC * CC) {
        int o = i / CC, c = i - o * CC;
        d_projT[c * CC + o] = proj_w[i];
    }
}

// ---------------------------------------------------------------------------
// Kernel 1: fused window attention. One CTA per 7x7 window (1024 CTAs).
// LN1 + shifted-window gather + QKV + per-head softmax-attention + proj +
// residual, scattered back with the within-window inverse roll.
// ---------------------------------------------------------------------------
#define A_STRIDE   97    // conflict-free row stride for [49][96] tiles
#define QKV_STRIDE 291   // [49][288]
#define ATTN_SMEM  ((TT*A_STRIDE + TT*QKV_STRIDE + TT*TT) * 4)

__global__ __launch_bounds__(256)
void attn_kernel(const float* __restrict__ x,
                 const float* __restrict__ n1g, const float* __restrict__ n1b,
                 const float* __restrict__ qkv_b,
                 const float* __restrict__ proj_b) {
    extern __shared__ float sm[];
    float* A   = sm;                       // LN'd window input, later reused as attn O
    float* QKV = A + TT * A_STRIDE;
    float* S   = QKV + TT * QKV_STRIDE;    // [49][49] one head at a time

    const int tid  = threadIdx.x;
    const int lane = tid & 31;
    const int warp = tid >> 5;
    const int bw = blockIdx.x;
    const int b  = bw >> 6;
    const int wi = (bw >> 3) & 7;
    const int wj = bw & 7;

    // --- 1. gather (roll -3,-3) + LayerNorm1, one warp per token ---
    for (int t = warp; t < TT; t += 8) {
        int ti = t / WS_, tj = t - (t / WS_) * WS_;
        int r = (wi * WS_ + ti + 3) % HH;
        int c = (wj * WS_ + tj + 3) % WW;
        const float* row = x + ((size_t)(b * LL_ + r * WW + c)) * CC;
        float v0 = row[lane], v1 = row[lane + 32], v2 = row[lane + 64];
        float s = v0 + v1 + v2;
        #pragma unroll
        for (int o = 16; o; o >>= 1) s += __shfl_xor_sync(~0u, s, o);
        float m = s * (1.0f / 96.0f);
        float d0 = v0 - m, d1 = v1 - m, d2 = v2 - m;
        float vv = d0 * d0 + d1 * d1 + d2 * d2;
        #pragma unroll
        for (int o = 16; o; o >>= 1) vv += __shfl_xor_sync(~0u, vv, o);
        float inv = rsqrtf(vv * (1.0f / 96.0f) + 1e-5f);
        A[t * A_STRIDE + lane]      = d0 * inv * n1g[lane]      + n1b[lane];
        A[t * A_STRIDE + lane + 32] = d1 * inv * n1g[lane + 32] + n1b[lane + 32];
        A[t * A_STRIDE + lane + 64] = d2 * inv * n1g[lane + 64] + n1b[lane + 64];
    }
    __syncthreads();

    // --- 2. QKV = A @ qkv_w^T + b : 72 groups of 4 outputs x 49 tokens ---
    for (int idx = tid; idx < 72 * TT; idx += 256) {
        int t = idx % TT, og = idx / TT;
        int o = og * 4;
        float a0 = qkv_b[o], a1 = qkv_b[o + 1], a2 = qkv_b[o + 2], a3 = qkv_b[o + 3];
        #pragma unroll 8
        for (int c = 0; c < CC; c++) {
            float av = A[t * A_STRIDE + c];
            float4 wv = *reinterpret_cast<const float4*>(&d_qkvT[c * 288 + o]);
            a0 += av * wv.x; a1 += av * wv.y; a2 += av * wv.z; a3 += av * wv.w;
        }
        float* q = &QKV[t * QKV_STRIDE + o];
        q[0] = a0; q[1] = a1; q[2] = a2; q[3] = a3;
    }
    __syncthreads();

    // --- 3. per-head attention (heads sequential, S reused) ---
    #pragma unroll 1
    for (int h = 0; h < NHD; h++) {
        const int qo = h * 32, ko = 96 + h * 32, vo = 192 + h * 32;
        for (int idx = tid; idx < TT * TT; idx += 256) {
            int i = idx / TT, j = idx % TT;
            float acc = 0.0f;
            #pragma unroll
            for (int d = 0; d < 32; d++)
                acc += QKV[i * QKV_STRIDE + qo + d] * QKV[j * QKV_STRIDE + ko + d];
            S[idx] = acc * 0.17677669529663687f;   // 1/sqrt(32)
        }
        __syncthreads();
        // softmax: one warp per row (49 entries -> lane and lane+32)
        for (int r = warp; r < TT; r += 8) {
            float a0 = S[r * TT + lane];
            float a1 = (lane < 17) ? S[r * TT + 32 + lane] : -1e30f;
            float mx = fmaxf(a0, a1);
            #pragma unroll
            for (int o = 16; o; o >>= 1) mx = fmaxf(mx, __shfl_xor_sync(~0u, mx, o));
            float e0 = expf(a0 - mx);
            float e1 = (lane < 17) ? expf(a1 - mx) : 0.0f;
            float ss = e0 + e1;
            #pragma unroll
            for (int o = 16; o; o >>= 1) ss += __shfl_xor_sync(~0u, ss, o);
            float inv = 1.0f / ss;
            S[r * TT + lane] = e0 * inv;
            if (lane < 17) S[r * TT + 32 + lane] = e1 * inv;
        }
        __syncthreads();
        // O = S @ V, written into A (A is dead after QKV)
        for (int idx = tid; idx < TT * 32; idx += 256) {
            int t = idx >> 5, d = idx & 31;
            float acc = 0.0f;
            #pragma unroll
            for (int j = 0; j < TT; j++)
                acc += S[t * TT + j] * QKV[j * QKV_STRIDE + vo + d];
            A[t * A_STRIDE + h * 32 + d] = acc;
        }
        __syncthreads();
    }

    // --- 4. proj + residual, scatter with within-window roll (+3,+3) ---
    for (int idx = tid; idx < 24 * TT; idx += 256) {
        int t = idx % TT, cog = idx / TT;
        int co = cog * 4;
        float a0 = proj_b[co], a1 = proj_b[co + 1], a2 = proj_b[co + 2], a3 = proj_b[co + 3];
        #pragma unroll 8
        for (int c = 0; c < CC; c++) {
            float ov = A[t * A_STRIDE + c];
            float4 wv = *reinterpret_cast<const float4*>(&d_projT[c * CC + co]);
            a0 += ov * wv.x; a1 += ov * wv.y; a2 += ov * wv.z; a3 += ov * wv.w;
        }
        int ti = t / WS_, tj = t - (t / WS_) * WS_;
        int dr = wi * WS_ + (ti + 3) % WS_;
        int dc = wj * WS_ + (tj + 3) % WS_;
        size_t off = ((size_t)(b * LL_ + dr * WW + dc)) * CC + co;
        float4 xr = *reinterpret_cast<const float4*>(&x[off]);
        float4 res = make_float4(xr.x + a0, xr.y + a1, xr.z + a2, xr.w + a3);
        *reinterpret_cast<float4*>(&d_x1[off]) = res;
    }
}

// ---------------------------------------------------------------------------
// Kernel 2: fused TM-FFN. 16 tokens per CTA (3136 CTAs).
// LN2 -> LN_ffn -> sigmoid(pin) -> log-literals -> masked-sum-exp clauses ->
// tm_out -> gated blend + residual.
// ---------------------------------------------------------------------------
#define W_STRIDE  97
#define LL_STRIDE 777
#define CL_STRIDE 132
#define TB 16
#define FFN_SMEM  ((TB*W_STRIDE + TB*LL_STRIDE + TB*CL_STRIDE) * 4)

__global__ __launch_bounds__(256)
void ffn_kernel(const float* __restrict__ n2g, const float* __restrict__ n2b,
                const float* __restrict__ nfg, const float* __restrict__ nfb,
                const float* __restrict__ pin_b,
                const float* __restrict__ tm_out,
                const float* __restrict__ gate,
                float* __restrict__ out) {
    extern __shared__ float sm[];
    float* W  = sm;                       // [16][96] double-LN'd input
    float* LG = W + TB * W_STRIDE;        // [16][768] log-literals
    float* CL = LG + TB * LL_STRIDE;      // [16][128] clause values

    const int tid  = threadIdx.x;
    const int lane = tid & 31;
    const int warp = tid >> 5;
    const size_t t0 = (size_t)blockIdx.x * TB;

    // --- 1. LN2 then LN_ffn (one warp per token) ---
    for (int tt = warp; tt < TB; tt += 8) {
        const float* row = d_x1 + (t0 + tt) * CC;
        float v0 = row[lane], v1 = row[lane + 32], v2 = row[lane + 64];
        float s = v0 + v1 + v2;
        #pragma unroll
        for (int o = 16; o; o >>= 1) s += __shfl_xor_sync(~0u, s, o);
        float m = s * (1.0f / 96.0f);
        float d0 = v0 - m, d1 = v1 - m, d2 = v2 - m;
        float vv = d0 * d0 + d1 * d1 + d2 * d2;
        #pragma unroll
        for (int o = 16; o; o >>= 1) vv += __shfl_xor_sync(~0u, vv, o);
        float inv = rsqrtf(vv * (1.0f / 96.0f) + 1e-5f);
        float z0 = d0 * inv * n2g[lane]      + n2b[lane];
        float z1 = d1 * inv * n2g[lane + 32] + n2b[lane + 32];
        float z2 = d2 * inv * n2g[lane + 64] + n2b[lane + 64];
        // second LN
        float s2 = z0 + z1 + z2;
        #pragma unroll
        for (int o = 16; o; o >>= 1) s2 += __shfl_xor_sync(~0u, s2, o);
        float m2 = s2 * (1.0f / 96.0f);
        float e0 = z0 - m2, e1 = z1 - m2, e2 = z2 - m2;
        float v2s = e0 * e0 + e1 * e1 + e2 * e2;
        #pragma unroll
        for (int o = 16; o; o >>= 1) v2s += __shfl_xor_sync(~0u, v2s, o);
        float inv2 = rsqrtf(v2s * (1.0f / 96.0f) + 1e-5f);
        W[tt * W_STRIDE + lane]      = e0 * inv2 * nfg[lane]      + nfb[lane];
        W[tt * W_STRIDE + lane + 32] = e1 * inv2 * nfg[lane + 32] + nfb[lane + 32];
        W[tt * W_STRIDE + lane + 64] = e2 * inv2 * nfg[lane + 64] + nfb[lane + 64];
    }
    __syncthreads();

    // --- 2. y = sigmoid(W @ pin_w^T + b); log-literals ---
    for (int idx = tid; idx < (HID_ / 4) * TB; idx += 256) {
        int t = idx & (TB - 1), hg = idx >> 4;
        int h = hg * 4;
        float a0 = pin_b[h], a1 = pin_b[h + 1], a2 = pin_b[h + 2], a3 = pin_b[h + 3];
        #pragma unroll 8
        for (int c = 0; c < CC; c++) {
            float wv = W[t * W_STRIDE + c];
            float4 p = *reinterpret_cast<const float4*>(&d_pinT[c * HID_ + h]);
            a0 += wv * p.x; a1 += wv * p.y; a2 += wv * p.z; a3 += wv * p.w;
        }
        float y0 = 1.0f / (1.0f + expf(-a0));
        float y1 = 1.0f / (1.0f + expf(-a1));
        float y2 = 1.0f / (1.0f + expf(-a2));
        float y3 = 1.0f / (1.0f + expf(-a3));
        float* lp = &LG[t * LL_STRIDE + h];
        float* lq = &LG[t * LL_STRIDE + HID_ + h];
        lp[0] = logf(fminf(fmaxf(y0, 1e-6f), 1.0f));
        lp[1] = logf(fminf(fmaxf(y1, 1e-6f), 1.0f));
        lp[2] = logf(fminf(fmaxf(y2, 1e-6f), 1.0f));
        lp[3] = logf(fminf(fmaxf(y3, 1e-6f), 1.0f));
        lq[0] = logf(fminf(fmaxf(1.0f - y0, 1e-6f), 1.0f));
        lq[1] = logf(fminf(fmaxf(1.0f - y1, 1e-6f), 1.0f));
        lq[2] = logf(fminf(fmaxf(1.0f - y2, 1e-6f), 1.0f));
        lq[3] = logf(fminf(fmaxf(1.0f - y3, 1e-6f), 1.0f));
    }
    __syncthreads();

    // --- 3. clauses = exp(loglits @ mask^T) ---
    for (int idx = tid; idx < (NCL_ / 4) * TB; idx += 256) {
        int t = idx & (TB - 1), jg = idx >> 4;
        int j = jg * 4;
        float a0 = 0.f, a1 = 0.f, a2 = 0.f, a3 = 0.f;
        #pragma unroll 8
        for (int i = 0; i < TWOH; i++) {
            float lv = LG[t * LL_STRIDE + i];
            float4 mv = *reinterpret_cast<const float4*>(&d_maskT[i * NCL_ + j]);
            a0 += lv * mv.x; a1 += lv * mv.y; a2 += lv * mv.z; a3 += lv * mv.w;
        }
        float* cl = &CL[t * CL_STRIDE + j];
        cl[0] = expf(a0); cl[1] = expf(a1); cl[2] = expf(a2); cl[3] = expf(a3);
    }
    __syncthreads();

    // --- 4. logits = clauses @ tm_out; gated blend + residual ---
    const float g = 1.0f / (1.0f + expf(-gate[0]));
    for (int idx = tid; idx < (CC / 4) * TB; idx += 256) {
        int cg = idx % (CC / 4), t = idx / (CC / 4);
        int c = cg * 4;
        float a0 = 0.f, a1 = 0.f, a2 = 0.f, a3 = 0.f;
        #pragma unroll 8
        for (int j = 0; j < NCL_; j++) {
            float cv = CL[t * CL_STRIDE + j];
            float4 ov = *reinterpret_cast<const float4*>(&tm_out[j * CC + c]);
            a0 += cv * ov.x; a1 += cv * ov.y; a2 += cv * ov.z; a3 += cv * ov.w;
        }
        float s0 = 1.0f / (1.0f + expf(-a0));
        float s1 = 1.0f / (1.0f + expf(-a1));
        float s2 = 1.0f / (1.0f + expf(-a2));
        float s3 = 1.0f / (1.0f + expf(-a3));
        size_t off = (t0 + t) * CC + c;
        float4 xr = *reinterpret_cast<const float4*>(&d_x1[off]);
        float4 res = make_float4(xr.x + g * a0 + (1.0f - g) * s0,
                                 xr.y + g * a1 + (1.0f - g) * s1,
                                 xr.z + g * a2 + (1.0f - g) * s2,
                                 xr.w + g * a3 + (1.0f - g) * s3);
        *reinterpret_cast<float4*>(&out[off]) = res;
    }
}

// ---------------------------------------------------------------------------
extern "C" void kernel_launch(void* const* d_in, const int* in_sizes, int n_in,
                              void* d_out, int out_size) {
    (void)in_sizes; (void)n_in; (void)out_size;
    const float* x      = (const float*)d_in[0];
    const float* n1g    = (const float*)d_in[1];
    const float* n1b    = (const float*)d_in[2];
    const float* qkv_w  = (const float*)d_in[3];
    const float* qkv_b  = (const float*)d_in[4];
    const float* proj_w = (const float*)d_in[5];
    const float* proj_b = (const float*)d_in[6];
    const float* n2g    = (const float*)d_in[7];
    const float* n2b    = (const float*)d_in[8];
    const float* nfg    = (const float*)d_in[9];
    const float* nfb    = (const float*)d_in[10];
    const float* pin_w  = (const float*)d_in[11];
    const float* pin_b  = (const float*)d_in[12];
    const float* tm_inc = (const float*)d_in[13];
    const float* tm_out = (const float*)d_in[14];
    const float* gate   = (const float*)d_in[15];
    float* out = (float*)d_out;

    cudaFuncSetAttribute(attn_kernel, cudaFuncAttributeMaxDynamicSharedMemorySize, ATTN_SMEM);
    cudaFuncSetAttribute(ffn_kernel,  cudaFuncAttributeMaxDynamicSharedMemorySize, FFN_SMEM);

    // prep covers 98304 + 36864 + 27648 + 9216 = 172032 elements = 672 * 256
    prep_kernel<<<672, 256>>>(tm_inc, pin_w, qkv_w, proj_w);
    attn_kernel<<<BB * 64, 256, ATTN_SMEM>>>(x, n1g, n1b, qkv_b, proj_b);
    ffn_kernel<<<LL_ * BB / TB, 256, FFN_SMEM>>>(n2g, n2b, nfg, nfb, pin_b, tm_out, gate, out);
}

// round 4
// speedup vs baseline: 2.3603x; 2.3603x over previous
#include <cuda_runtime.h>
#include <math.h>

// Problem constants
#define BB   16
#define HH   56
#define WW   56
#define CC   96
#define LL_  3136        // 56*56
#define NHD  3
#define WS_  7
#define TT   49
#define HID_ 384
#define NCL_ 128
#define TWOH 768

#define LOG_EPS -13.815511f   // log(1e-6)

// scratch (device globals)
__device__ float d_x1[BB * LL_ * CC];
__device__ float d_maskT[TWOH * NCL_];   // binarized tm_inc, [i][j]
__device__ float d_pinT[CC * HID_];      // pin_w^T [c][h]
__device__ float d_qkvT[CC * 288];       // qkv_w^T [c][o]
__device__ float d_projT[CC * CC];       // proj_w^T [c][o]

// ---------------------------------------------------------------------------
__global__ void prep_kernel(const float* __restrict__ tm_inc,
                            const float* __restrict__ pin_w,
                            const float* __restrict__ qkv_w,
                            const float* __restrict__ proj_w) {
    int i = blockIdx.x * 256 + threadIdx.x;
    if (i < NCL_ * TWOH) {
        int j = i / TWOH, k = i - j * TWOH;
        d_maskT[k * NCL_ + j] = (tm_inc[i] > 0.0f) ? 1.0f : 0.0f;
        return;
    }
    i -= NCL_ * TWOH;
    if (i < HID_ * CC) {
        int h = i / CC, c = i - h * CC;
        d_pinT[c * HID_ + h] = pin_w[i];
        return;
    }
    i -= HID_ * CC;
    if (i < 288 * CC) {
        int o = i / CC, c = i - o * CC;
        d_qkvT[c * 288 + o] = qkv_w[i];
        return;
    }
    i -= 288 * CC;
    if (i < CC * CC) {
        int o = i / CC, c = i - o * CC;
        d_projT[c * CC + o] = proj_w[i];
    }
}

// ---------------------------------------------------------------------------
// Kernel 1: fused window attention. One CTA per 7x7 window (1024 CTAs),
// 256 threads, register-tiled 4x4 GEMM fragments.
// ---------------------------------------------------------------------------
#define TP 52                       // padded token count (49 -> 52)
#define AT_SZ  (96 * TP)            // feature-major LN input / later O^T
#define QT_SZ  (96 * TP)
#define KT_SZ  (96 * TP)
#define V_STR  100
#define V_SZ   (TP * V_STR)
#define S3_SZ  (3 * 49 * 49)
#define ATTN_SMEM ((AT_SZ + QT_SZ + KT_SZ + V_SZ + S3_SZ) * 4)

__global__ __launch_bounds__(256)
void attn_kernel(const float* __restrict__ x,
                 const float* __restrict__ n1g, const float* __restrict__ n1b,
                 const float* __restrict__ qkv_b,
                 const float* __restrict__ proj_b) {
    extern __shared__ float sm[];
    float* AT = sm;                 // [96][52]  A^T, later O^T
    float* QT = AT + AT_SZ;         // [96][52]
    float* KT = QT + QT_SZ;         // [96][52]
    float* V  = KT + KT_SZ;         // [52][100]
    float* S3 = V + V_SZ;           // [3][49][49]

    const int tid  = threadIdx.x;
    const int lane = tid & 31;
    const int warp = tid >> 5;
    const int bw = blockIdx.x;
    const int b  = bw >> 6;
    const int wi = (bw >> 3) & 7;
    const int wj = bw & 7;

    // --- 1. gather (roll -3,-3) + LayerNorm1 -> AT[c][t]
    for (int t = warp; t < TT; t += 8) {
        int ti = t / WS_, tj = t - ti * WS_;
        int r = (wi * WS_ + ti + 3) % HH;
        int c = (wj * WS_ + tj + 3) % WW;
        const float* row = x + ((size_t)(b * LL_ + r * WW + c)) * CC;
        float v0 = row[lane], v1 = row[lane + 32], v2 = row[lane + 64];
        float s = v0 + v1 + v2;
        #pragma unroll
        for (int o = 16; o; o >>= 1) s += __shfl_xor_sync(~0u, s, o);
        float m = s * (1.0f / 96.0f);
        float d0 = v0 - m, d1 = v1 - m, d2 = v2 - m;
        float vv = d0 * d0 + d1 * d1 + d2 * d2;
        #pragma unroll
        for (int o = 16; o; o >>= 1) vv += __shfl_xor_sync(~0u, vv, o);
        float inv = rsqrtf(vv * (1.0f / 96.0f) + 1e-5f);
        AT[lane * TP + t]        = d0 * inv * n1g[lane]      + n1b[lane];
        AT[(lane + 32) * TP + t] = d1 * inv * n1g[lane + 32] + n1b[lane + 32];
        AT[(lane + 64) * TP + t] = d2 * inv * n1g[lane + 64] + n1b[lane + 64];
    }
    __syncthreads();

    // --- 2. QKV = A @ qkv_w^T + b, 4 tok x 4 out tiles (13 x 72 = 936) ---
    for (int idx = tid; idx < 13 * 72; idx += 256) {
        int og = idx % 72, tg = idx / 72;
        int o = og * 4;
        float a[4][4];
        #pragma unroll
        for (int ii = 0; ii < 4; ii++)
            #pragma unroll
            for (int k = 0; k < 4; k++) a[ii][k] = 0.0f;
        const float* atb = &AT[tg * 4];
        #pragma unroll 4
        for (int c = 0; c < CC; c++) {
            float4 av = *reinterpret_cast<const float4*>(&atb[c * TP]);
            float4 wv = *reinterpret_cast<const float4*>(&d_qkvT[c * 288 + o]);
            float avv[4] = {av.x, av.y, av.z, av.w};
            float wvv[4] = {wv.x, wv.y, wv.z, wv.w};
            #pragma unroll
            for (int ii = 0; ii < 4; ii++)
                #pragma unroll
                for (int k = 0; k < 4; k++) a[ii][k] += avv[ii] * wvv[k];
        }
        #pragma unroll
        for (int k = 0; k < 4; k++) {
            int ok = o + k;
            float bias = qkv_b[ok];
            #pragma unroll
            for (int ii = 0; ii < 4; ii++) {
                int t = tg * 4 + ii;
                float v = a[ii][k] + bias;
                if (ok < 96)       QT[ok * TP + t] = v;
                else if (ok < 192) KT[(ok - 96) * TP + t] = v;
                else               V[t * V_STR + (ok - 192)] = v;
            }
        }
    }
    __syncthreads();

    // --- 3. S = Q K^T * scale, tiles: 3 heads x 13 x 13 = 507 ---
    for (int idx = tid; idx < 507; idx += 256) {
        int h = idx / 169; int r = idx - h * 169;
        int ig = r / 13, jg = r - (r / 13) * 13;
        float a[4][4];
        #pragma unroll
        for (int ii = 0; ii < 4; ii++)
            #pragma unroll
            for (int jj = 0; jj < 4; jj++) a[ii][jj] = 0.0f;
        const float* qb = &QT[h * 32 * TP + ig * 4];
        const float* kb = &KT[h * 32 * TP + jg * 4];
        #pragma unroll 8
        for (int d = 0; d < 32; d++) {
            float4 qv = *reinterpret_cast<const float4*>(&qb[d * TP]);
            float4 kv = *reinterpret_cast<const float4*>(&kb[d * TP]);
            float qq[4] = {qv.x, qv.y, qv.z, qv.w};
            float kk[4] = {kv.x, kv.y, kv.z, kv.w};
            #pragma unroll
            for (int ii = 0; ii < 4; ii++)
                #pragma unroll
                for (int jj = 0; jj < 4; jj++) a[ii][jj] += qq[ii] * kk[jj];
        }
        #pragma unroll
        for (int ii = 0; ii < 4; ii++) {
            int i = ig * 4 + ii;
            if (i < TT) {
                #pragma unroll
                for (int jj = 0; jj < 4; jj++) {
                    int j = jg * 4 + jj;
                    if (j < TT)
                        S3[h * (TT * TT) + i * TT + j] = a[ii][jj] * 0.17677669529663687f;
                }
            }
        }
    }
    __syncthreads();

    // --- softmax over 147 rows ---
    for (int row = warp; row < 3 * TT; row += 8) {
        float* Sr = &S3[row * TT];
        float a0 = Sr[lane];
        float a1 = (lane < 17) ? Sr[32 + lane] : -1e30f;
        float mx = fmaxf(a0, a1);
        #pragma unroll
        for (int o = 16; o; o >>= 1) mx = fmaxf(mx, __shfl_xor_sync(~0u, mx, o));
        float e0 = __expf(a0 - mx);
        float e1 = (lane < 17) ? __expf(a1 - mx) : 0.0f;
        float ss = e0 + e1;
        #pragma unroll
        for (int o = 16; o; o >>= 1) ss += __shfl_xor_sync(~0u, ss, o);
        float inv = __fdividef(1.0f, ss);
        Sr[lane] = e0 * inv;
        if (lane < 17) Sr[32 + lane] = e1 * inv;
    }
    __syncthreads();

    // --- 4. O = S @ V -> AT[(h*32+d)][i], tiles: 3 x 13 x 8 = 312 ---
    for (int idx = tid; idx < 312; idx += 256) {
        int h = idx / 104; int r = idx - h * 104;
        int ig = r >> 3, dg = r & 7;
        float a[4][4];
        #pragma unroll
        for (int ii = 0; ii < 4; ii++)
            #pragma unroll
            for (int k = 0; k < 4; k++) a[ii][k] = 0.0f;
        // clamp pad rows to 48 (results discarded)
        const float* S0 = &S3[h * (TT * TT) + min(ig * 4 + 0, 48) * TT];
        const float* S1 = &S3[h * (TT * TT) + min(ig * 4 + 1, 48) * TT];
        const float* S2 = &S3[h * (TT * TT) + min(ig * 4 + 2, 48) * TT];
        const float* Sx = &S3[h * (TT * TT) + min(ig * 4 + 3, 48) * TT];
        const float* Vb = &V[h * 32 + dg * 4];
        #pragma unroll 7
        for (int j = 0; j < TT; j++) {
            float4 vv = *reinterpret_cast<const float4*>(&Vb[j * V_STR]);
            float vvv[4] = {vv.x, vv.y, vv.z, vv.w};
            float ss[4] = {S0[j], S1[j], S2[j], Sx[j]};
            #pragma unroll
            for (int ii = 0; ii < 4; ii++)
                #pragma unroll
                for (int k = 0; k < 4; k++) a[ii][k] += ss[ii] * vvv[k];
        }
        #pragma unroll
        for (int k = 0; k < 4; k++)
            #pragma unroll
            for (int ii = 0; ii < 4; ii++)
                AT[(h * 32 + dg * 4 + k) * TP + ig * 4 + ii] = a[ii][k];
    }
    __syncthreads();

    // --- 5. proj + residual scatter, tiles 13 x 24 = 312 ---
    for (int idx = tid; idx < 312; idx += 256) {
        int tg = idx % 13, cg = idx / 13;
        int co = cg * 4;
        float a[4][4];
        #pragma unroll
        for (int ii = 0; ii < 4; ii++)
            #pragma unroll
            for (int k = 0; k < 4; k++) a[ii][k] = 0.0f;
        const float* atb = &AT[tg * 4];
        #pragma unroll 4
        for (int c = 0; c < CC; c++) {
            float4 ov = *reinterpret_cast<const float4*>(&atb[c * TP]);
            float4 wv = *reinterpret_cast<const float4*>(&d_projT[c * CC + co]);
            float oo[4] = {ov.x, ov.y, ov.z, ov.w};
            float ww[4] = {wv.x, wv.y, wv.z, wv.w};
            #pragma unroll
            for (int ii = 0; ii < 4; ii++)
                #pragma unroll
                for (int k = 0; k < 4; k++) a[ii][k] += oo[ii] * ww[k];
        }
        #pragma unroll
        for (int ii = 0; ii < 4; ii++) {
            int t = tg * 4 + ii;
            if (t < TT) {
                int ti = t / WS_, tj = t - ti * WS_;
                int dr = wi * WS_ + (ti + 3) % WS_;
                int dc = wj * WS_ + (tj + 3) % WS_;
                size_t off = ((size_t)(b * LL_ + dr * WW + dc)) * CC + co;
                float4 xr = *reinterpret_cast<const float4*>(&x[off]);
                float4 res = make_float4(xr.x + a[ii][0] + proj_b[co],
                                         xr.y + a[ii][1] + proj_b[co + 1],
                                         xr.z + a[ii][2] + proj_b[co + 2],
                                         xr.w + a[ii][3] + proj_b[co + 3]);
                *reinterpret_cast<float4*>(&d_x1[off]) = res;
            }
        }
    }
}

// ---------------------------------------------------------------------------
// Kernel 2: fused TM-FFN. 16 tokens / CTA, 128 threads, 4x4 register tiles,
// feature-major smem staging for LDS.128 broadcast loads.
// ---------------------------------------------------------------------------
#define TB 16
#define FFN_SMEM ((96 * TB + TWOH * TB + NCL_ * TB) * 4)   // 62 KB

__global__ __launch_bounds__(128)
void ffn_kernel(const float* __restrict__ n2g, const float* __restrict__ n2b,
                const float* __restrict__ nfg, const float* __restrict__ nfb,
                const float* __restrict__ pin_b,
                const float* __restrict__ tm_out,
                const float* __restrict__ gate,
                float* __restrict__ out) {
    extern __shared__ float sm[];
    float* WT = sm;                   // [96][16]
    float* LT = WT + 96 * TB;         // [768][16]
    float* CT = LT + TWOH * TB;       // [128][16]

    const int tid  = threadIdx.x;
    const int lane = tid & 31;
    const int warp = tid >> 5;
    const int tg4  = (tid & 3) * 4;
    const size_t t0 = (size_t)blockIdx.x * TB;

    // --- 1. LN2 then LN_ffn -> WT[c][t] ---
    for (int tt = warp; tt < TB; tt += 4) {
        const float* row = d_x1 + (t0 + tt) * CC;
        float v0 = row[lane], v1 = row[lane + 32], v2 = row[lane + 64];
        float s = v0 + v1 + v2;
        #pragma unroll
        for (int o = 16; o; o >>= 1) s += __shfl_xor_sync(~0u, s, o);
        float m = s * (1.0f / 96.0f);
        float d0 = v0 - m, d1 = v1 - m, d2 = v2 - m;
        float vv = d0 * d0 + d1 * d1 + d2 * d2;
        #pragma unroll
        for (int o = 16; o; o >>= 1) vv += __shfl_xor_sync(~0u, vv, o);
        float inv = rsqrtf(vv * (1.0f / 96.0f) + 1e-5f);
        float z0 = d0 * inv * n2g[lane]      + n2b[lane];
        float z1 = d1 * inv * n2g[lane + 32] + n2b[lane + 32];
        float z2 = d2 * inv * n2g[lane + 64] + n2b[lane + 64];
        float s2 = z0 + z1 + z2;
        #pragma unroll
        for (int o = 16; o; o >>= 1) s2 += __shfl_xor_sync(~0u, s2, o);
        float m2 = s2 * (1.0f / 96.0f);
        float e0 = z0 - m2, e1 = z1 - m2, e2 = z2 - m2;
        float v2s = e0 * e0 + e1 * e1 + e2 * e2;
        #pragma unroll
        for (int o = 16; o; o >>= 1) v2s += __shfl_xor_sync(~0u, v2s, o);
        float inv2 = rsqrtf(v2s * (1.0f / 96.0f) + 1e-5f);
        WT[lane * TB + tt]        = e0 * inv2 * nfg[lane]      + nfb[lane];
        WT[(lane + 32) * TB + tt] = e1 * inv2 * nfg[lane + 32] + nfb[lane + 32];
        WT[(lane + 64) * TB + tt] = e2 * inv2 * nfg[lane + 64] + nfb[lane + 64];
    }
    __syncthreads();

    // --- 2. pin GEMM + log-literals (softplus form) ---
    for (int hg = tid >> 2; hg < HID_ / 4; hg += 32) {
        int h = hg * 4;
        float a[4][4];
        #pragma unroll
        for (int ii = 0; ii < 4; ii++)
            #pragma unroll
            for (int k = 0; k < 4; k++) a[ii][k] = 0.0f;
        #pragma unroll 8
        for (int c = 0; c < CC; c++) {
            float4 wv = *reinterpret_cast<const float4*>(&WT[c * TB + tg4]);
            float4 p  = *reinterpret_cast<const float4*>(&d_pinT[c * HID_ + h]);
            float ww[4] = {wv.x, wv.y, wv.z, wv.w};
            float pp[4] = {p.x, p.y, p.z, p.w};
            #pragma unroll
            for (int ii = 0; ii < 4; ii++)
                #pragma unroll
                for (int k = 0; k < 4; k++) a[ii][k] += ww[ii] * pp[k];
        }
        #pragma unroll
        for (int k = 0; k < 4; k++) {
            float bias = pin_b[h + k];
            #pragma unroll
            for (int ii = 0; ii < 4; ii++) {
                float v = a[ii][k] + bias;
                // log(sig(v)) = -softplus(-v);  log(1-sig(v)) = -softplus(v)
                float spn = (v < -15.f) ? -v : __logf(1.0f + __expf(-v));
                float spp = (v >  15.f) ?  v : __logf(1.0f + __expf(v));
                LT[(h + k) * TB + tg4 + ii]          = fmaxf(-spn, LOG_EPS);
                LT[(h + k + HID_) * TB + tg4 + ii]   = fmaxf(-spp, LOG_EPS);
            }
        }
    }
    __syncthreads();

    // --- 3. clauses = exp(loglits @ mask^T) ---
    {
        int j = (tid >> 2) * 4;
        float a[4][4];
        #pragma unroll
        for (int ii = 0; ii < 4; ii++)
            #pragma unroll
            for (int k = 0; k < 4; k++) a[ii][k] = 0.0f;
        #pragma unroll 8
        for (int i = 0; i < TWOH; i++) {
            float4 lv = *reinterpret_cast<const float4*>(&LT[i * TB + tg4]);
            float4 mv = *reinterpret_cast<const float4*>(&d_maskT[i * NCL_ + j]);
            float ll[4] = {lv.x, lv.y, lv.z, lv.w};
            float mm[4] = {mv.x, mv.y, mv.z, mv.w};
            #pragma unroll
            for (int ii = 0; ii < 4; ii++)
                #pragma unroll
                for (int k = 0; k < 4; k++) a[ii][k] += ll[ii] * mm[k];
        }
        #pragma unroll
        for (int k = 0; k < 4; k++)
            #pragma unroll
            for (int ii = 0; ii < 4; ii++)
                CT[(j + k) * TB + tg4 + ii] = __expf(a[ii][k]);
    }
    __syncthreads();

    // --- 4. logits = clauses @ tm_out; gated blend + residual ---
    if (tid < 96) {
        int c = (tid >> 2) * 4;
        float a[4][4];
        #pragma unroll
        for (int ii = 0; ii < 4; ii++)
            #pragma unroll
            for (int k = 0; k < 4; k++) a[ii][k] = 0.0f;
        #pragma unroll 8
        for (int j = 0; j < NCL_; j++) {
            float4 cv = *reinterpret_cast<const float4*>(&CT[j * TB + tg4]);
            float4 ov = *reinterpret_cast<const float4*>(&tm_out[j * CC + c]);
            float ccv[4] = {cv.x, cv.y, cv.z, cv.w};
            float oo[4] = {ov.x, ov.y, ov.z, ov.w};
            #pragma unroll
            for (int ii = 0; ii < 4; ii++)
                #pragma unroll
                for (int k = 0; k < 4; k++) a[ii][k] += ccv[ii] * oo[k];
        }
        float g = __fdividef(1.0f, 1.0f + __expf(-gate[0]));
        #pragma unroll
        for (int ii = 0; ii < 4; ii++) {
            size_t off = (t0 + tg4 + ii) * CC + c;
            float4 xr = *reinterpret_cast<const float4*>(&d_x1[off]);
            float r[4];
            #pragma unroll
            for (int k = 0; k < 4; k++) {
                float lg = a[ii][k];
                float sg = __fdividef(1.0f, 1.0f + __expf(-lg));
                r[k] = g * lg + (1.0f - g) * sg;
            }
            float4 res = make_float4(xr.x + r[0], xr.y + r[1], xr.z + r[2], xr.w + r[3]);
            *reinterpret_cast<float4*>(&out[off]) = res;
        }
    }
}

// ---------------------------------------------------------------------------
extern "C" void kernel_launch(void* const* d_in, const int* in_sizes, int n_in,
                              void* d_out, int out_size) {
    (void)in_sizes; (void)n_in; (void)out_size;
    const float* x      = (const float*)d_in[0];
    const float* n1g    = (const float*)d_in[1];
    const float* n1b    = (const float*)d_in[2];
    const float* qkv_w  = (const float*)d_in[3];
    const float* qkv_b  = (const float*)d_in[4];
    const float* proj_w = (const float*)d_in[5];
    const float* proj_b = (const float*)d_in[6];
    const float* n2g    = (const float*)d_in[7];
    const float* n2b    = (const float*)d_in[8];
    const float* nfg    = (const float*)d_in[9];
    const float* nfb    = (const float*)d_in[10];
    const float* pin_w  = (const float*)d_in[11];
    const float* pin_b  = (const float*)d_in[12];
    const float* tm_inc = (const float*)d_in[13];
    const float* tm_out = (const float*)d_in[14];
    const float* gate   = (const float*)d_in[15];
    float* out = (float*)d_out;

    cudaFuncSetAttribute(attn_kernel, cudaFuncAttributeMaxDynamicSharedMemorySize, ATTN_SMEM);
    cudaFuncSetAttribute(ffn_kernel,  cudaFuncAttributeMaxDynamicSharedMemorySize, FFN_SMEM);

    prep_kernel<<<672, 256>>>(tm_inc, pin_w, qkv_w, proj_w);
    attn_kernel<<<BB * 64, 256, ATTN_SMEM>>>(x, n1g, n1b, qkv_b, proj_b);
    ffn_kernel<<<LL_ * BB / TB, 128, FFN_SMEM>>>(n2g, n2b, nfg, nfb, pin_b, tm_out, gate, out);
}

// round 6
// speedup vs baseline: 2.9226x; 1.2382x over previous
#include <cuda_runtime.h>
#include <cuda_bf16.h>
#include <math.h>
#include <stdint.h>

// Problem constants
#define BB   16
#define HH   56
#define WW   56
#define CC   96
#define LL_  3136        // 56*56
#define NHD  3
#define WS_  7
#define TT   49
#define HID_ 384
#define NCL_ 128
#define TWOH 768
#define NTOT (BB * LL_)  // 50176 tokens

#define LOG_EPS -13.815511f   // log(1e-6)

// ---------------------------------------------------------------------------
// device-global scratch (no allocation allowed)
// ---------------------------------------------------------------------------
__device__ float d_x1[NTOT * CC];                  // residual after attention
__device__ unsigned int d_ll[(size_t)NTOT * TWOH]; // packed loglits: hi | lo<<16 (bf16)
__device__ __nv_bfloat16 d_maskB[NCL_ * TWOH];     // binarized tm_inc (bf16, [j][i])
__device__ float d_pinT[CC * HID_];                // pin_w^T [c][h]
__device__ float d_qkvT[CC * 288];                 // qkv_w^T [c][o]
__device__ float d_projT[CC * CC];                 // proj_w^T [c][o]

__device__ __forceinline__ unsigned pack_ll(float l) {
    __nv_bfloat16 h = __float2bfloat16(l);
    __nv_bfloat16 lo = __float2bfloat16(l - __bfloat162float(h));
    return (unsigned)__bfloat16_as_ushort(h) | ((unsigned)__bfloat16_as_ushort(lo) << 16);
}

// ---------------------------------------------------------------------------
// Prep: binarize mask -> bf16 [j][i]; transpose weights
// ---------------------------------------------------------------------------
__global__ void prep_kernel(const float* __restrict__ tm_inc,
                            const float* __restrict__ pin_w,
                            const float* __restrict__ qkv_w,
                            const float* __restrict__ proj_w) {
    int i = blockIdx.x * 256 + threadIdx.x;
    if (i < NCL_ * TWOH) {
        d_maskB[i] = __float2bfloat16((tm_inc[i] > 0.0f) ? 1.0f : 0.0f);
        return;
    }
    i -= NCL_ * TWOH;
    if (i < HID_ * CC) {
        int h = i / CC, c = i - h * CC;
        d_pinT[c * HID_ + h] = pin_w[i];
        return;
    }
    i -= HID_ * CC;
    if (i < 288 * CC) {
        int o = i / CC, c = i - o * CC;
        d_qkvT[c * 288 + o] = qkv_w[i];
        return;
    }
    i -= 288 * CC;
    if (i < CC * CC) {
        int o = i / CC, c = i - o * CC;
        d_projT[c * CC + o] = proj_w[i];
    }
}

// ---------------------------------------------------------------------------
// Kernel 1: fused window attention (unchanged — 4x4 register tiles)
// ---------------------------------------------------------------------------
#define TP 52
#define AT_SZ  (96 * TP)
#define QT_SZ  (96 * TP)
#define KT_SZ  (96 * TP)
#define V_STR  100
#define V_SZ   (TP * V_STR)
#define S3_SZ  (3 * 49 * 49)
#define ATTN_SMEM ((AT_SZ + QT_SZ + KT_SZ + V_SZ + S3_SZ) * 4)

__global__ __launch_bounds__(256)
void attn_kernel(const float* __restrict__ x,
                 const float* __restrict__ n1g, const float* __restrict__ n1b,
                 const float* __restrict__ qkv_b,
                 const float* __restrict__ proj_b) {
    extern __shared__ float sm[];
    float* AT = sm;
    float* QT = AT + AT_SZ;
    float* KT = QT + QT_SZ;
    float* V  = KT + KT_SZ;
    float* S3 = V + V_SZ;

    const int tid  = threadIdx.x;
    const int lane = tid & 31;
    const int warp = tid >> 5;
    const int bw = blockIdx.x;
    const int b  = bw >> 6;
    const int wi = (bw >> 3) & 7;
    const int wj = bw & 7;

    for (int t = warp; t < TT; t += 8) {
        int ti = t / WS_, tj = t - ti * WS_;
        int r = (wi * WS_ + ti + 3) % HH;
        int c = (wj * WS_ + tj + 3) % WW;
        const float* row = x + ((size_t)(b * LL_ + r * WW + c)) * CC;
        float v0 = row[lane], v1 = row[lane + 32], v2 = row[lane + 64];
        float s = v0 + v1 + v2;
        #pragma unroll
        for (int o = 16; o; o >>= 1) s += __shfl_xor_sync(~0u, s, o);
        float m = s * (1.0f / 96.0f);
        float d0 = v0 - m, d1 = v1 - m, d2 = v2 - m;
        float vv = d0 * d0 + d1 * d1 + d2 * d2;
        #pragma unroll
        for (int o = 16; o; o >>= 1) vv += __shfl_xor_sync(~0u, vv, o);
        float inv = rsqrtf(vv * (1.0f / 96.0f) + 1e-5f);
        AT[lane * TP + t]        = d0 * inv * n1g[lane]      + n1b[lane];
        AT[(lane + 32) * TP + t] = d1 * inv * n1g[lane + 32] + n1b[lane + 32];
        AT[(lane + 64) * TP + t] = d2 * inv * n1g[lane + 64] + n1b[lane + 64];
    }
    __syncthreads();

    for (int idx = tid; idx < 13 * 72; idx += 256) {
        int og = idx % 72, tg = idx / 72;
        int o = og * 4;
        float a[4][4];
        #pragma unroll
        for (int ii = 0; ii < 4; ii++)
            #pragma unroll
            for (int k = 0; k < 4; k++) a[ii][k] = 0.0f;
        const float* atb = &AT[tg * 4];
        #pragma unroll 4
        for (int c = 0; c < CC; c++) {
            float4 av = *reinterpret_cast<const float4*>(&atb[c * TP]);
            float4 wv = *reinterpret_cast<const float4*>(&d_qkvT[c * 288 + o]);
            float avv[4] = {av.x, av.y, av.z, av.w};
            float wvv[4] = {wv.x, wv.y, wv.z, wv.w};
            #pragma unroll
            for (int ii = 0; ii < 4; ii++)
                #pragma unroll
                for (int k = 0; k < 4; k++) a[ii][k] += avv[ii] * wvv[k];
        }
        #pragma unroll
        for (int k = 0; k < 4; k++) {
            int ok = o + k;
            float bias = qkv_b[ok];
            #pragma unroll
            for (int ii = 0; ii < 4; ii++) {
                int t = tg * 4 + ii;
                float v = a[ii][k] + bias;
                if (ok < 96)       QT[ok * TP + t] = v;
                else if (ok < 192) KT[(ok - 96) * TP + t] = v;
                else               V[t * V_STR + (ok - 192)] = v;
            }
        }
    }
    __syncthreads();

    for (int idx = tid; idx < 507; idx += 256) {
        int h = idx / 169; int r = idx - h * 169;
        int ig = r / 13, jg = r - (r / 13) * 13;
        float a[4][4];
        #pragma unroll
        for (int ii = 0; ii < 4; ii++)
            #pragma unroll
            for (int jj = 0; jj < 4; jj++) a[ii][jj] = 0.0f;
        const float* qb = &QT[h * 32 * TP + ig * 4];
        const float* kb = &KT[h * 32 * TP + jg * 4];
        #pragma unroll 8
        for (int d = 0; d < 32; d++) {
            float4 qv = *reinterpret_cast<const float4*>(&qb[d * TP]);
            float4 kv = *reinterpret_cast<const float4*>(&kb[d * TP]);
            float qq[4] = {qv.x, qv.y, qv.z, qv.w};
            float kk[4] = {kv.x, kv.y, kv.z, kv.w};
            #pragma unroll
            for (int ii = 0; ii < 4; ii++)
                #pragma unroll
                for (int jj = 0; jj < 4; jj++) a[ii][jj] += qq[ii] * kk[jj];
        }
        #pragma unroll
        for (int ii = 0; ii < 4; ii++) {
            int i = ig * 4 + ii;
            if (i < TT) {
                #pragma unroll
                for (int jj = 0; jj < 4; jj++) {
                    int j = jg * 4 + jj;
                    if (j < TT)
                        S3[h * (TT * TT) + i * TT + j] = a[ii][jj] * 0.17677669529663687f;
                }
            }
        }
    }
    __syncthreads();

    for (int row = warp; row < 3 * TT; row += 8) {
        float* Sr = &S3[row * TT];
        float a0 = Sr[lane];
        float a1 = (lane < 17) ? Sr[32 + lane] : -1e30f;
        float mx = fmaxf(a0, a1);
        #pragma unroll
        for (int o = 16; o; o >>= 1) mx = fmaxf(mx, __shfl_xor_sync(~0u, mx, o));
        float e0 = __expf(a0 - mx);
        float e1 = (lane < 17) ? __expf(a1 - mx) : 0.0f;
        float ss = e0 + e1;
        #pragma unroll
        for (int o = 16; o; o >>= 1) ss += __shfl_xor_sync(~0u, ss, o);
        float inv = __fdividef(1.0f, ss);
        Sr[lane] = e0 * inv;
        if (lane < 17) Sr[32 + lane] = e1 * inv;
    }
    __syncthreads();

    for (int idx = tid; idx < 312; idx += 256) {
        int h = idx / 104; int r = idx - h * 104;
        int ig = r >> 3, dg = r & 7;
        float a[4][4];
        #pragma unroll
        for (int ii = 0; ii < 4; ii++)
            #pragma unroll
            for (int k = 0; k < 4; k++) a[ii][k] = 0.0f;
        const float* S0 = &S3[h * (TT * TT) + min(ig * 4 + 0, 48) * TT];
        const float* S1 = &S3[h * (TT * TT) + min(ig * 4 + 1, 48) * TT];
        const float* S2 = &S3[h * (TT * TT) + min(ig * 4 + 2, 48) * TT];
        const float* Sx = &S3[h * (TT * TT) + min(ig * 4 + 3, 48) * TT];
        const float* Vb = &V[h * 32 + dg * 4];
        #pragma unroll 7
        for (int j = 0; j < TT; j++) {
            float4 vv = *reinterpret_cast<const float4*>(&Vb[j * V_STR]);
            float vvv[4] = {vv.x, vv.y, vv.z, vv.w};
            float ss[4] = {S0[j], S1[j], S2[j], Sx[j]};
            #pragma unroll
            for (int ii = 0; ii < 4; ii++)
                #pragma unroll
                for (int k = 0; k < 4; k++) a[ii][k] += ss[ii] * vvv[k];
        }
        #pragma unroll
        for (int k = 0; k < 4; k++)
            #pragma unroll
            for (int ii = 0; ii < 4; ii++)
                AT[(h * 32 + dg * 4 + k) * TP + ig * 4 + ii] = a[ii][k];
    }
    __syncthreads();

    for (int idx = tid; idx < 312; idx += 256) {
        int tg = idx % 13, cg = idx / 13;
        int co = cg * 4;
        float a[4][4];
        #pragma unroll
        for (int ii = 0; ii < 4; ii++)
            #pragma unroll
            for (int k = 0; k < 4; k++) a[ii][k] = 0.0f;
        const float* atb = &AT[tg * 4];
        #pragma unroll 4
        for (int c = 0; c < CC; c++) {
            float4 ov = *reinterpret_cast<const float4*>(&atb[c * TP]);
            float4 wv = *reinterpret_cast<const float4*>(&d_projT[c * CC + co]);
            float oo[4] = {ov.x, ov.y, ov.z, ov.w};
            float ww[4] = {wv.x, wv.y, wv.z, wv.w};
            #pragma unroll
            for (int ii = 0; ii < 4; ii++)
                #pragma unroll
                for (int k = 0; k < 4; k++) a[ii][k] += oo[ii] * ww[k];
        }
        #pragma unroll
        for (int ii = 0; ii < 4; ii++) {
            int t = tg * 4 + ii;
            if (t < TT) {
                int ti = t / WS_, tj = t - ti * WS_;
                int dr = wi * WS_ + (ti + 3) % WS_;
                int dc = wj * WS_ + (tj + 3) % WS_;
                size_t off = ((size_t)(b * LL_ + dr * WW + dc)) * CC + co;
                float4 xr = *reinterpret_cast<const float4*>(&x[off]);
                float4 res = make_float4(xr.x + a[ii][0] + proj_b[co],
                                         xr.y + a[ii][1] + proj_b[co + 1],
                                         xr.z + a[ii][2] + proj_b[co + 2],
                                         xr.w + a[ii][3] + proj_b[co + 3]);
                *reinterpret_cast<float4*>(&d_x1[off]) = res;
            }
        }
    }
}

// ---------------------------------------------------------------------------
// Kernel 2: pin stage. 16 tokens / CTA, 128 threads. LN2 -> LN_ffn ->
// pin GEMM -> softplus loglits -> packed hi/lo bf16 to gmem.
// ---------------------------------------------------------------------------
#define TB 16
#define PIN_SMEM (96 * TB * 4)

__global__ __launch_bounds__(128)
void pin_kernel(const float* __restrict__ n2g, const float* __restrict__ n2b,
                const float* __restrict__ nfg, const float* __restrict__ nfb,
                const float* __restrict__ pin_b) {
    extern __shared__ float smw[];
    float* WT = smw;                  // [96][16]

    const int tid  = threadIdx.x;
    const int lane = tid & 31;
    const int warp = tid >> 5;
    const int tg4  = (tid & 3) * 4;
    const size_t t0 = (size_t)blockIdx.x * TB;

    for (int tt = warp; tt < TB; tt += 4) {
        const float* row = d_x1 + (t0 + tt) * CC;
        float v0 = row[lane], v1 = row[lane + 32], v2 = row[lane + 64];
        float s = v0 + v1 + v2;
        #pragma unroll
        for (int o = 16; o; o >>= 1) s += __shfl_xor_sync(~0u, s, o);
        float m = s * (1.0f / 96.0f);
        float d0 = v0 - m, d1 = v1 - m, d2 = v2 - m;
        float vv = d0 * d0 + d1 * d1 + d2 * d2;
        #pragma unroll
        for (int o = 16; o; o >>= 1) vv += __shfl_xor_sync(~0u, vv, o);
        float inv = rsqrtf(vv * (1.0f / 96.0f) + 1e-5f);
        float z0 = d0 * inv * n2g[lane]      + n2b[lane];
        float z1 = d1 * inv * n2g[lane + 32] + n2b[lane + 32];
        float z2 = d2 * inv * n2g[lane + 64] + n2b[lane + 64];
        float s2 = z0 + z1 + z2;
        #pragma unroll
        for (int o = 16; o; o >>= 1) s2 += __shfl_xor_sync(~0u, s2, o);
        float m2 = s2 * (1.0f / 96.0f);
        float e0 = z0 - m2, e1 = z1 - m2, e2 = z2 - m2;
        float v2s = e0 * e0 + e1 * e1 + e2 * e2;
        #pragma unroll
        for (int o = 16; o; o >>= 1) v2s += __shfl_xor_sync(~0u, v2s, o);
        float inv2 = rsqrtf(v2s * (1.0f / 96.0f) + 1e-5f);
        WT[lane * TB + tt]        = e0 * inv2 * nfg[lane]      + nfb[lane];
        WT[(lane + 32) * TB + tt] = e1 * inv2 * nfg[lane + 32] + nfb[lane + 32];
        WT[(lane + 64) * TB + tt] = e2 * inv2 * nfg[lane + 64] + nfb[lane + 64];
    }
    __syncthreads();

    for (int hg = tid >> 2; hg < HID_ / 4; hg += 32) {
        int h = hg * 4;
        float a[4][4];
        #pragma unroll
        for (int ii = 0; ii < 4; ii++)
            #pragma unroll
            for (int k = 0; k < 4; k++) a[ii][k] = 0.0f;
        #pragma unroll 8
        for (int c = 0; c < CC; c++) {
            float4 wv = *reinterpret_cast<const float4*>(&WT[c * TB + tg4]);
            float4 p  = *reinterpret_cast<const float4*>(&d_pinT[c * HID_ + h]);
            float ww[4] = {wv.x, wv.y, wv.z, wv.w};
            float pp[4] = {p.x, p.y, p.z, p.w};
            #pragma unroll
            for (int ii = 0; ii < 4; ii++)
                #pragma unroll
                for (int k = 0; k < 4; k++) a[ii][k] += ww[ii] * pp[k];
        }
        float bias[4] = {pin_b[h], pin_b[h + 1], pin_b[h + 2], pin_b[h + 3]};
        #pragma unroll
        for (int ii = 0; ii < 4; ii++) {
            unsigned u1[4], u2[4];
            #pragma unroll
            for (int k = 0; k < 4; k++) {
                float v = a[ii][k] + bias[k];
                // log(sig(v)) = -softplus(-v);  log(1-sig(v)) = -softplus(v)
                float spn = (v < -15.f) ? -v : __logf(1.0f + __expf(-v));
                float spp = (v >  15.f) ?  v : __logf(1.0f + __expf(v));
                u1[k] = pack_ll(fmaxf(-spn, LOG_EPS));
                u2[k] = pack_ll(fmaxf(-spp, LOG_EPS));
            }
            size_t t = t0 + tg4 + ii;
            *reinterpret_cast<uint4*>(&d_ll[t * TWOH + h]) =
                make_uint4(u1[0], u1[1], u1[2], u1[3]);
            *reinterpret_cast<uint4*>(&d_ll[t * TWOH + HID_ + h]) =
                make_uint4(u2[0], u2[1], u2[2], u2[3]);
        }
    }
}

// ---------------------------------------------------------------------------
// Kernel 3: clause GEMM via mma.sync bf16 (legacy tensor path, sm_80 PTX).
// 392 CTAs x 128 tokens, 256 threads (8 warps). Each warp: 16 tokens x 128
// clauses, K=768 in 12 chunks of 64, hi+lo split accumulated in fp32.
// Epilogue: exp -> CLT[j][t] smem -> fp32 tm_out GEMM -> gated blend.
// ---------------------------------------------------------------------------
#define NTOK 128
#define KC   64               // K per chunk
#define CSTR 72               // smem row stride (bf16) — conflict-free frags
#define MB_OFF 0
#define LH_OFF (128 * CSTR)
#define LO_OFF (2 * 128 * CSTR)
#define CLT_STR 132
#define CLA_SMEM ((NCL_ * CLT_STR) * 4)   // 67584 B (chunk area 55296 fits inside)

__device__ __forceinline__ void mma16816(float* d, uint32_t a0, uint32_t a1,
                                         uint32_t a2, uint32_t a3,
                                         uint32_t b0, uint32_t b1) {
    asm volatile(
        "mma.sync.aligned.m16n8k16.row.col.f32.bf16.bf16.f32 "
        "{%0,%1,%2,%3}, {%4,%5,%6,%7}, {%8,%9}, {%0,%1,%2,%3};"
        : "+f"(d[0]), "+f"(d[1]), "+f"(d[2]), "+f"(d[3])
        : "r"(a0), "r"(a1), "r"(a2), "r"(a3), "r"(b0), "r"(b1));
}

__global__ __launch_bounds__(256)
void clause_kernel(const float* __restrict__ tm_out,
                   const float* __restrict__ gate,
                   float* __restrict__ out) {
    extern __shared__ char smc[];
    __nv_bfloat16* SB = reinterpret_cast<__nv_bfloat16*>(smc);
    float* CLT = reinterpret_cast<float*>(smc);

    const int tid  = threadIdx.x;
    const int wid  = tid >> 5;
    const int lane = tid & 31;
    const int qr   = lane >> 2;        // 0..7
    const int qc   = (lane & 3) * 2;   // 0,2,4,6
    const int t0   = blockIdx.x * NTOK;
    const int r0   = wid * 16;         // this warp's token rows

    float acc[64];                     // 16 n-tiles x 4 regs
    #pragma unroll
    for (int i = 0; i < 64; i++) acc[i] = 0.0f;

    for (int ch = 0; ch < 12; ch++) {
        __syncthreads();   // previous chunk's frag reads done
        // stage mask chunk: 128 clauses x 64 bf16, stride 72
        for (int idx = tid; idx < 1024; idx += 256) {
            int row = idx >> 3, col = idx & 7;
            uint4 v = *reinterpret_cast<const uint4*>(
                &d_maskB[row * TWOH + ch * KC + col * 8]);
            *reinterpret_cast<uint4*>(&SB[MB_OFF + row * CSTR + col * 8]) = v;
        }
        // stage loglit chunk: 128 tokens x 64 packed -> hi tile + lo tile
        for (int idx = tid; idx < 2048; idx += 256) {
            int row = idx >> 4, col = idx & 15;
            uint4 p = *reinterpret_cast<const uint4*>(
                &d_ll[(size_t)(t0 + row) * TWOH + ch * KC + col * 4]);
            uint32_t h01 = (p.x & 0xffffu) | (p.y << 16);
            uint32_t h23 = (p.z & 0xffffu) | (p.w << 16);
            uint32_t l01 = (p.x >> 16) | (p.y & 0xffff0000u);
            uint32_t l23 = (p.z >> 16) | (p.w & 0xffff0000u);
            int off = row * CSTR + col * 4;
            *reinterpret_cast<uint2*>(&SB[LH_OFF + off]) = make_uint2(h01, h23);
            *reinterpret_cast<uint2*>(&SB[LO_OFF + off]) = make_uint2(l01, l23);
        }
        __syncthreads();

        #pragma unroll
        for (int ks = 0; ks < 4; ks++) {
            const int k0 = ks * 16;
            // A fragments (hi and lo), row-major 16x16
            uint32_t ah0 = *reinterpret_cast<const uint32_t*>(
                &SB[LH_OFF + (r0 + qr) * CSTR + k0 + qc]);
            uint32_t ah1 = *reinterpret_cast<const uint32_t*>(
                &SB[LH_OFF + (r0 + qr + 8) * CSTR + k0 + qc]);
            uint32_t ah2 = *reinterpret_cast<const uint32_t*>(
                &SB[LH_OFF + (r0 + qr) * CSTR + k0 + qc + 8]);
            uint32_t ah3 = *reinterpret_cast<const uint32_t*>(
                &SB[LH_OFF + (r0 + qr + 8) * CSTR + k0 + qc + 8]);
            uint32_t al0 = *reinterpret_cast<const uint32_t*>(
                &SB[LO_OFF + (r0 + qr) * CSTR + k0 + qc]);
            uint32_t al1 = *reinterpret_cast<const uint32_t*>(
                &SB[LO_OFF + (r0 + qr + 8) * CSTR + k0 + qc]);
            uint32_t al2 = *reinterpret_cast<const uint32_t*>(
                &SB[LO_OFF + (r0 + qr) * CSTR + k0 + qc + 8]);
            uint32_t al3 = *reinterpret_cast<const uint32_t*>(
                &SB[LO_OFF + (r0 + qr + 8) * CSTR + k0 + qc + 8]);
            #pragma unroll
            for (int nt = 0; nt < 16; nt++) {
                int n = nt * 8 + qr;
                uint32_t b0 = *reinterpret_cast<const uint32_t*>(
                    &SB[MB_OFF + n * CSTR + k0 + qc]);
                uint32_t b1 = *reinterpret_cast<const uint32_t*>(
                    &SB[MB_OFF + n * CSTR + k0 + qc + 8]);
                mma16816(&acc[nt * 4], ah0, ah1, ah2, ah3, b0, b1);
                mma16816(&acc[nt * 4], al0, al1, al2, al3, b0, b1);
            }
        }
    }
    __syncthreads();   // all frag reads done before CLT overwrites staging area

    // exp + transposed store: CLT[j][t]
    #pragma unroll
    for (int nt = 0; nt < 16; nt++) {
        int j = nt * 8 + qc;
        CLT[j * CLT_STR + r0 + qr]           = __expf(acc[nt * 4 + 0]);
        CLT[(j + 1) * CLT_STR + r0 + qr]     = __expf(acc[nt * 4 + 1]);
        CLT[j * CLT_STR + r0 + qr + 8]       = __expf(acc[nt * 4 + 2]);
        CLT[(j + 1) * CLT_STR + r0 + qr + 8] = __expf(acc[nt * 4 + 3]);
    }
    __syncthreads();

    // logits = clauses @ tm_out; gated blend + residual
    const float g = __fdividef(1.0f, 1.0f + __expf(-gate[0]));
    for (int idx = tid; idx < 32 * 24; idx += 256) {
        int tg = idx & 31, cg = idx >> 5;
        float a[4][4];
        #pragma unroll
        for (int ii = 0; ii < 4; ii++)
            #pragma unroll
            for (int k = 0; k < 4; k++) a[ii][k] = 0.0f;
        const float* clb = &CLT[tg * 4];
        const float* ob  = &tm_out[cg * 4];
        #pragma unroll 8
        for (int j = 0; j < NCL_; j++) {
            float4 cv = *reinterpret_cast<const float4*>(&clb[j * CLT_STR]);
            float4 ov = *reinterpret_cast<const float4*>(&ob[j * CC]);
            float cc[4] = {cv.x, cv.y, cv.z, cv.w};
            float oo[4] = {ov.x, ov.y, ov.z, ov.w};
            #pragma unroll
            for (int ii = 0; ii < 4; ii++)
                #pragma unroll
                for (int k = 0; k < 4; k++) a[ii][k] += cc[ii] * oo[k];
        }
        #pragma unroll
        for (int ii = 0; ii < 4; ii++) {
            size_t off = (size_t)(t0 + tg * 4 + ii) * CC + cg * 4;
            float4 xr = *reinterpret_cast<const float4*>(&d_x1[off]);
            float r[4];
            #pragma unroll
            for (int k = 0; k < 4; k++) {
                float lg = a[ii][k];
                float sg = __fdividef(1.0f, 1.0f + __expf(-lg));
                r[k] = g * lg + (1.0f - g) * sg;
            }
            float4 res = make_float4(xr.x + r[0], xr.y + r[1], xr.z + r[2], xr.w + r[3]);
            *reinterpret_cast<float4*>(&out[off]) = res;
        }
    }
}

// ---------------------------------------------------------------------------
extern "C" void kernel_launch(void* const* d_in, const int* in_sizes, int n_in,
                              void* d_out, int out_size) {
    (void)in_sizes; (void)n_in; (void)out_size;
    const float* x      = (const float*)d_in[0];
    const float* n1g    = (const float*)d_in[1];
    const float* n1b    = (const float*)d_in[2];
    const float* qkv_w  = (const float*)d_in[3];
    const float* qkv_b  = (const float*)d_in[4];
    const float* proj_w = (const float*)d_in[5];
    const float* proj_b = (const float*)d_in[6];
    const float* n2g    = (const float*)d_in[7];
    const float* n2b    = (const float*)d_in[8];
    const float* nfg    = (const float*)d_in[9];
    const float* nfb    = (const float*)d_in[10];
    const float* pin_w  = (const float*)d_in[11];
    const float* pin_b  = (const float*)d_in[12];
    const float* tm_inc = (const float*)d_in[13];
    const float* tm_out = (const float*)d_in[14];
    const float* gate   = (const float*)d_in[15];
    float* out = (float*)d_out;

    cudaFuncSetAttribute(attn_kernel,   cudaFuncAttributeMaxDynamicSharedMemorySize, ATTN_SMEM);
    cudaFuncSetAttribute(clause_kernel, cudaFuncAttributeMaxDynamicSharedMemorySize, CLA_SMEM);

    prep_kernel<<<672, 256>>>(tm_inc, pin_w, qkv_w, proj_w);
    attn_kernel<<<BB * 64, 256, ATTN_SMEM>>>(x, n1g, n1b, qkv_b, proj_b);
    pin_kernel<<<NTOT / TB, 128, PIN_SMEM>>>(n2g, n2b, nfg, nfb, pin_b);
    clause_kernel<<<NTOT / NTOK, 256, CLA_SMEM>>>(tm_out, gate, out);
}